// round 2
// baseline (speedup 1.0000x reference)
#include <cuda_runtime.h>
#include <cstdint>

// Problem constants (fixed shapes for this problem)
#define T_LEN 4096
#define B_LEN 4096

// LUT: log2-spaced piecewise-linear table of
//   g(s) = (1/sqrt(2pi)) * int_{-5}^{5} (1 - tanh(sqrt(s)*z)^2) exp(-z^2/2) dz
// indexed directly by float bits of s. 64 bins/octave, s in [2^-16, 2^10).
#define OCTAVES 26
#define NLUT (OCTAVES * 64)       // 1664 bins
#define NB   (NLUT + 1)
#define BASE_BITS 0x37800000u     // float bits of 2^-16
#define BASE_OFF  56832u          // (BASE_BITS >> 14)
#define EPS_S 1.52587890625e-05f  // 2^-16 added to u^2 so s >= 2^-16 always

__device__ float  g_bound[NB];
__device__ float2 g_lut[NLUT];

// ---------------------------------------------------------------------------
// Boundary values of g via composite Simpson on [0,5] (even integrand -> x2),
// n=1024 intervals, f32 evals, double accumulation. One warp per boundary.
// ---------------------------------------------------------------------------
__global__ void build_bounds_kernel() {
    int j = blockIdx.x;
    int lane = threadIdx.x;
    unsigned bits = BASE_BITS + ((unsigned)j << 17);
    float s = __uint_as_float(bits);
    float delta = sqrtf(s);

    const int   n = 1024;
    const float h = 5.0f / (float)n;
    double acc = 0.0;
    for (int i = lane; i <= n; i += 32) {
        float z = h * (float)i;
        float t = tanhf(delta * z);
        float f = (1.0f - t * t) * expf(-0.5f * z * z);
        float coef = (i == 0 || i == n) ? 1.0f : ((i & 1) ? 4.0f : 2.0f);
        acc += (double)(f * coef);
    }
    #pragma unroll
    for (int o = 16; o; o >>= 1)
        acc += __shfl_down_sync(0xffffffffu, acc, o);
    if (lane == 0) {
        double integ = acc * ((double)h / 3.0);
        g_bound[j] = (float)(2.0 * integ * 0.3989422804014327);
    }
}

__global__ void build_lut_kernel() {
    int i = blockIdx.x * blockDim.x + threadIdx.x;
    if (i < NLUT) {
        float a = g_bound[i];
        float b = g_bound[i + 1];
        g_lut[i] = make_float2(a, (b - a) * (1.0f / 131072.0f));
    }
}

// ---------------------------------------------------------------------------
// Main scan: one thread per batch row, 1 warp per block, 128 blocks.
// Latency-bound on the per-step RAW chain:
//   FFMA(s) -> SHF -> LOP3 -> LDS.64 -> FFMA(g) -> FFMA(k)
// u prefetched into registers (8x LDG.128 per 32-step tile, ping-pong).
// ---------------------------------------------------------------------------
__global__ __launch_bounds__(32, 1)
void scan_kernel(const float* __restrict__ u, float* __restrict__ out) {
    __shared__ float2 lut_s[NLUT];

    int lane = threadIdx.x;
    int b = blockIdx.x * 32 + lane;

    // Stage LUT into shared (float4 copies)
    {
        const float4* src = (const float4*)g_lut;    // NLUT*8/16 = 832
        float4* dst = (float4*)lut_s;
        #pragma unroll 4
        for (int i = lane; i < NLUT / 2; i += 32) dst[i] = src[i];
    }
    __syncwarp();

    const float4* __restrict__ urow = (const float4*)(u + (size_t)b * T_LEN);
    float* __restrict__ zrow = out + (size_t)b * (T_LEN + 1);
    zrow[0] = 0.0f;
    float* __restrict__ zw = zrow + 1;

    float4 bufA[8], bufB[8];
    #pragma unroll
    for (int j = 0; j < 8; ++j) bufA[j] = __ldg(urow + j);

    float k = 0.0f, v = 0.0f;

    // One step of the recurrence. Chain entry: s = k*k + (u*u + eps).
    // LDS address = lut_base + ((bits>>14) & 0x1FFF8) - BASE_OFF; written so
    // ptxas can fold the static smem base minus BASE_OFF into the LDS imm.
#define STEP(UIN, ZP, TI) do {                                              \
        float uin = (UIN);                                                  \
        v = fmaf(0.2f, uin, 0.8f * v);                                      \
        float q  = fmaf(0.28f, k, 0.52f * v);                               \
        float kk = 0.8f * k;                                                \
        float uu = fmaf(uin, uin, EPS_S);                                   \
        float s  = fmaf(k, k, uu);                                          \
        unsigned bits = __float_as_uint(s);                                 \
        unsigned off  = (bits >> 14) & 0x1FFF8u;                            \
        float2 ab = *(const float2*)((const char*)lut_s + (off - BASE_OFF));\
        float fr = __uint2float_rn(bits & 0x1FFFFu);                        \
        float g  = fmaf(fr, ab.y, ab.x);                                    \
        k = fmaf(g, q, kk);                                                 \
        (ZP)[(TI)] = 2.1f * k;                                              \
    } while (0)

#define TILE(BUF, ZP) do {                                                  \
        _Pragma("unroll")                                                   \
        for (int c = 0; c < 8; ++c) {                                       \
            STEP((BUF)[c].x, ZP, 4 * c + 0);                                \
            STEP((BUF)[c].y, ZP, 4 * c + 1);                                \
            STEP((BUF)[c].z, ZP, 4 * c + 2);                                \
            STEP((BUF)[c].w, ZP, 4 * c + 3);                                \
        }                                                                   \
    } while (0)

    #pragma unroll 1
    for (int t2 = 0; t2 < T_LEN / 64; ++t2) {
        int tile0 = 2 * t2;

        // Prefetch tile0+1 into bufB, then consume bufA
        #pragma unroll
        for (int j = 0; j < 8; ++j) bufB[j] = __ldg(urow + (tile0 + 1) * 8 + j);
        TILE(bufA, zw + tile0 * 32);

        // Prefetch tile0+2 into bufA (if any), then consume bufB
        if (t2 < T_LEN / 64 - 1) {
            #pragma unroll
            for (int j = 0; j < 8; ++j) bufA[j] = __ldg(urow + (tile0 + 2) * 8 + j);
        }
        TILE(bufB, zw + (tile0 + 1) * 32);
    }
#undef TILE
#undef STEP
}

// ---------------------------------------------------------------------------
extern "C" void kernel_launch(void* const* d_in, const int* in_sizes, int n_in,
                              void* d_out, int out_size) {
    const float* u = (const float*)d_in[0];
    float* out = (float*)d_out;
    (void)in_sizes; (void)n_in; (void)out_size;

    build_bounds_kernel<<<NB, 32>>>();
    build_lut_kernel<<<(NLUT + 255) / 256, 256>>>();
    scan_kernel<<<B_LEN / 32, 32>>>(u, out);
}

// round 4
// speedup vs baseline: 1.4019x; 1.4019x over previous
#include <cuda_runtime.h>
#include <cstdint>

// Problem constants (fixed shapes for this problem)
#define T_LEN 4096
#define B_LEN 4096
#define NTILES (T_LEN / 32)

// LUT: log2-spaced piecewise-linear table of
//   g(s) = (1/sqrt(2pi)) * int_{-5}^{5} (1 - tanh(sqrt(s)*z)^2) exp(-z^2/2) dz
// indexed directly by float bits of s. 64 bins/octave, s in [2^-16, 2^10).
#define OCTAVES 26
#define NLUT (OCTAVES * 64)       // 1664
#define NB   (NLUT + 1)
#define BASE_BITS 0x37800000u     // float bits of 2^-16
#define BASE_OFF  56832u          // BASE_BITS >> 14
#define EPS_S 1.52587890625e-05f  // 2^-16, added to u^2 so s >= 2^-16 always

__device__ float  g_bound[NB];
__device__ float2 g_lut[NLUT];

// ---------------------------------------------------------------------------
// Boundary values of g via composite Simpson on [0,5] (even integrand -> x2),
// n=1024 intervals, f32 evals, double accumulation. One warp per boundary.
// ---------------------------------------------------------------------------
__global__ void build_bounds_kernel() {
    int j = blockIdx.x;
    int lane = threadIdx.x;
    unsigned bits = BASE_BITS + ((unsigned)j << 17);
    float delta = sqrtf(__uint_as_float(bits));

    const int   n = 1024;
    const float h = 5.0f / (float)n;
    double acc = 0.0;
    for (int i = lane; i <= n; i += 32) {
        float z = h * (float)i;
        float t = tanhf(delta * z);
        float f = (1.0f - t * t) * expf(-0.5f * z * z);
        float coef = (i == 0 || i == n) ? 1.0f : ((i & 1) ? 4.0f : 2.0f);
        acc += (double)(f * coef);
    }
    #pragma unroll
    for (int o = 16; o; o >>= 1)
        acc += __shfl_down_sync(0xffffffffu, acc, o);
    if (lane == 0) {
        double integ = acc * ((double)h / 3.0);
        g_bound[j] = (float)(2.0 * integ * 0.3989422804014327);
    }
}

__global__ void build_lut_kernel() {
    int i = blockIdx.x * blockDim.x + threadIdx.x;
    if (i < NLUT) {
        float a = g_bound[i];
        float b = g_bound[i + 1];
        g_lut[i] = make_float2(a, (b - a) * (1.0f / 131072.0f));
    }
}

// ---------------------------------------------------------------------------
// Warp-specialized scan. Block = 64 threads:
//   warp 0 (SMSP a): pure recurrence, chain-bound:
//       FFMA(s) -> SHF -> LOP3 -> LDS.64 -> FFMA(g) -> FFMA(k)
//   warp 1 (SMSP b): cp.async u prefetch (triple buffer), z drain smem->gmem.
// One __syncthreads() per 32-step tile.
// ---------------------------------------------------------------------------
__device__ __forceinline__ void prefetch_tile(const float* __restrict__ u,
                                              int b0, int tile,
                                              float* ubuf, int lane) {
    const float* src = u + (size_t)b0 * T_LEN + (size_t)tile * 32 + lane;
    unsigned sbase = (unsigned)__cvta_generic_to_shared(ubuf);
    #pragma unroll
    for (int r = 0; r < 32; ++r) {
        unsigned d = sbase + (unsigned)((r * 33 + lane) * 4);
        const float* s = src + (size_t)r * T_LEN;
        asm volatile("cp.async.ca.shared.global [%0], [%1], 4;" :: "r"(d), "l"(s));
    }
}

__global__ __launch_bounds__(64, 1)
void scan_kernel(const float* __restrict__ u, float* __restrict__ out) {
    __shared__ float2 lut_s[NLUT];
    __shared__ float  u_s[3][32 * 33];
    __shared__ float  z_s[2][32 * 33];

    int tid  = threadIdx.x;
    int lane = tid & 31;
    int wid  = tid >> 5;
    int b0 = blockIdx.x * 32;

    // Cooperative LUT stage (both warps, float4 copies)
    {
        const float4* src = (const float4*)g_lut;     // NLUT*8/16 = 832
        float4* dst = (float4*)lut_s;
        for (int i = tid; i < NLUT / 2; i += 64) dst[i] = src[i];
    }

    if (wid == 1) {
        prefetch_tile(u, b0, 0, u_s[0], lane);
        asm volatile("cp.async.commit_group;" ::: "memory");
        prefetch_tile(u, b0, 1, u_s[1], lane);
        asm volatile("cp.async.commit_group;" ::: "memory");
        asm volatile("cp.async.wait_group 1;" ::: "memory");
    } else {
        out[(size_t)(b0 + lane) * (T_LEN + 1)] = 0.0f;  // z_hist[:,0] = 0
    }
    __syncthreads();

    float k = 0.0f, W = 0.0f;   // W = v / 0.2 ; q = 0.28k + 0.104W

    #pragma unroll 1
    for (int t = 0; t < NTILES; ++t) {
        if (wid == 0) {
            // ---- compute warp: 32 steps, smem in / smem out ----
            const float* __restrict__ ut = &u_s[t % 3][lane * 33];
            float* __restrict__ zt = &z_s[t & 1][lane * 33];
            #pragma unroll
            for (int c = 0; c < 32; ++c) {
                float uin = ut[c];
                W = fmaf(0.8f, W, uin);
                float q  = fmaf(0.104f, W, 0.28f * k);
                float kk = 0.8f * k;
                float s  = fmaf(k, k, fmaf(uin, uin, EPS_S));
                unsigned bits = __float_as_uint(s);
                unsigned off  = (bits >> 14) & 0x1FFF8u;
                float2 ab = *(const float2*)((const char*)lut_s + (off - BASE_OFF));
                float fr = __uint2float_rn(bits & 0x1FFFFu);
                float g  = fmaf(fr, ab.y, ab.x);
                k = fmaf(g, q, kk);
                zt[c] = 2.1f * k;
            }
        } else {
            // ---- I/O warp ----
            if (t + 2 < NTILES)
                prefetch_tile(u, b0, t + 2, u_s[(t + 2) % 3], lane);
            asm volatile("cp.async.commit_group;" ::: "memory");
            if (t > 0) {
                // drain z tile t-1 (written during iteration t-1, bar-ordered)
                const float* zs = z_s[(t - 1) & 1];
                float* dst = out + (size_t)b0 * (T_LEN + 1) + 1
                           + (size_t)(t - 1) * 32 + lane;
                #pragma unroll
                for (int r = 0; r < 32; ++r)
                    dst[(size_t)r * (T_LEN + 1)] = zs[r * 33 + lane];
            }
            asm volatile("cp.async.wait_group 1;" ::: "memory");
        }
        __syncthreads();
    }

    if (wid == 1) {
        // drain final z tile (NTILES-1)
        const float* zs = z_s[(NTILES - 1) & 1];
        float* dst = out + (size_t)b0 * (T_LEN + 1) + 1
                   + (size_t)(NTILES - 1) * 32 + lane;
        #pragma unroll
        for (int r = 0; r < 32; ++r)
            dst[(size_t)r * (T_LEN + 1)] = zs[r * 33 + lane];
    }
}

// ---------------------------------------------------------------------------
extern "C" void kernel_launch(void* const* d_in, const int* in_sizes, int n_in,
                              void* d_out, int out_size) {
    const float* u = (const float*)d_in[0];
    float* out = (float*)d_out;
    (void)in_sizes; (void)n_in; (void)out_size;

    build_bounds_kernel<<<NB, 32>>>();
    build_lut_kernel<<<(NLUT + 255) / 256, 256>>>();
    scan_kernel<<<B_LEN / 32, 64>>>(u, out);
}

// round 7
// speedup vs baseline: 1.4433x; 1.0295x over previous
#include <cuda_runtime.h>
#include <cstdint>

// Problem constants (fixed shapes for this problem)
#define T_LEN 4096
#define B_LEN 4096
#define NTILES (T_LEN / 32)

// LUT: log2-spaced piecewise-linear table of
//   g(s) = (1/sqrt(2pi)) * int_{-5}^{5} (1 - tanh(sqrt(s)*z)^2) exp(-z^2/2) dz
// indexed directly by float bits of s. 64 bins/octave, s in [2^-16, 2^10).
#define OCTAVES 26
#define NLUT (OCTAVES * 64)       // 1664
#define NB   (NLUT + 1)
#define BASE_BITS 0x37800000u     // float bits of 2^-16
#define BASE_OFF  56832u          // BASE_BITS >> 14
#define EPS_S 1.52587890625e-05f  // 2^-16, added to u^2 so s >= 2^-16 always

__device__ float  g_bound[NB];
__device__ float2 g_lut[NLUT];

// ---------------------------------------------------------------------------
// Boundary values of g via composite Simpson on [0,5] (even integrand -> x2),
// n=1024 intervals, f32 evals, double accumulation. One warp per boundary.
// ---------------------------------------------------------------------------
__global__ void build_bounds_kernel() {
    int j = blockIdx.x;
    int lane = threadIdx.x;
    unsigned bits = BASE_BITS + ((unsigned)j << 17);
    float delta = sqrtf(__uint_as_float(bits));

    const int   n = 1024;
    const float h = 5.0f / (float)n;
    double acc = 0.0;
    for (int i = lane; i <= n; i += 32) {
        float z = h * (float)i;
        float t = tanhf(delta * z);
        float f = (1.0f - t * t) * expf(-0.5f * z * z);
        float coef = (i == 0 || i == n) ? 1.0f : ((i & 1) ? 4.0f : 2.0f);
        acc += (double)(f * coef);
    }
    #pragma unroll
    for (int o = 16; o; o >>= 1)
        acc += __shfl_down_sync(0xffffffffu, acc, o);
    if (lane == 0) {
        double integ = acc * ((double)h / 3.0);
        g_bound[j] = (float)(2.0 * integ * 0.3989422804014327);
    }
}

__global__ void build_lut_kernel() {
    int i = blockIdx.x * blockDim.x + threadIdx.x;
    if (i < NLUT) {
        float a = g_bound[i];
        float b = g_bound[i + 1];
        g_lut[i] = make_float2(a, (b - a) * (1.0f / 131072.0f));
    }
}

// ---------------------------------------------------------------------------
// Warp-specialized scan. Block = 64 threads.
// u_s layout (written by prefetch_tile): [row*33 + time], row=0..31 within
// the block's 32 batch rows, time=0..31 within the tile.
//   warp 0: ONLY the k-chain:
//       s=FFMA(k,k,uu) -> SHF -> LOP3 -> LDS.64(lut) -> FFMA(g) -> FFMA(k)
//     reading precomputed (uu, r) pairs; stores raw k to smem.
//   warp 1: cp.async u prefetch; runs the v/W recurrence ONE TILE AHEAD,
//     writing (uu, r)=(u^2+eps, 0.104*W) pairs; drains z (applies 2.1x).
// One __syncthreads() per 32-step tile.
// ---------------------------------------------------------------------------
__device__ __forceinline__ void prefetch_tile(const float* __restrict__ u,
                                              int b0, int tile,
                                              float* ubuf, int lane) {
    const float* src = u + (size_t)b0 * T_LEN + (size_t)tile * 32 + lane;
    unsigned sbase = (unsigned)__cvta_generic_to_shared(ubuf);
    #pragma unroll
    for (int r = 0; r < 32; ++r) {
        // row r, time lane  ->  ubuf[r*33 + lane]
        unsigned d = sbase + (unsigned)((r * 33 + lane) * 4);
        const float* s = src + (size_t)r * T_LEN;
        asm volatile("cp.async.ca.shared.global [%0], [%1], 4;" :: "r"(d), "l"(s));
    }
}

__global__ __launch_bounds__(64, 1)
void scan_kernel(const float* __restrict__ u, float* __restrict__ out) {
    __shared__ float2 lut_s[NLUT];
    __shared__ float  u_s[2][32 * 33];     // [row*33 + time]
    __shared__ float2 pair_s[2][32 * 33];  // [row*33 + time] = (uu, r)
    __shared__ float  z_s[2][32 * 33];     // [row*33 + time], raw k

    int tid  = threadIdx.x;
    int lane = tid & 31;
    int wid  = tid >> 5;
    int b0 = blockIdx.x * 32;

    // Cooperative LUT stage (both warps, float4 copies)
    {
        const float4* src = (const float4*)g_lut;     // NLUT*8/16 = 832
        float4* dst = (float4*)lut_s;
        for (int i = tid; i < NLUT / 2; i += 64) dst[i] = src[i];
    }

    float W = 0.0f;  // I/O warp's v-state: v = 0.2*W, W <- 0.8*W + u

    if (wid == 1) {
        prefetch_tile(u, b0, 0, u_s[0], lane);
        asm volatile("cp.async.commit_group;" ::: "memory");
        prefetch_tile(u, b0, 1, u_s[1], lane);
        asm volatile("cp.async.commit_group;" ::: "memory");
        asm volatile("cp.async.wait_group 1;" ::: "memory");
        // Build pairs for tile 0: lane = row, c = time
        float2* pp = &pair_s[0][lane * 33];
        #pragma unroll
        for (int c = 0; c < 32; ++c) {
            float uin = u_s[0][lane * 33 + c];
            W = fmaf(0.8f, W, uin);
            pp[c] = make_float2(fmaf(uin, uin, EPS_S), 0.104f * W);
        }
    } else {
        out[(size_t)(b0 + lane) * (T_LEN + 1)] = 0.0f;  // z_hist[:,0] = 0
    }
    __syncthreads();

    float k = 0.0f;

    #pragma unroll 1
    for (int t = 0; t < NTILES; ++t) {
        if (wid == 0) {
            // ---- compute warp: 32 chain steps (lane = row) ----
            const float2* __restrict__ pp = &pair_s[t & 1][lane * 33];
            float* __restrict__ zt = &z_s[t & 1][lane * 33];
            #pragma unroll
            for (int c = 0; c < 32; ++c) {
                float2 pr = pp[c];                  // hoistable LDS.64
                float q  = fmaf(0.28f, k, pr.y);
                float kk = 0.8f * k;
                float s  = fmaf(k, k, pr.x);
                unsigned bits = __float_as_uint(s);
                unsigned off  = (bits >> 14) & 0x1FFF8u;
                float2 ab = *(const float2*)((const char*)lut_s + (off - BASE_OFF));
                float fr = __uint2float_rn(bits & 0x1FFFFu);
                float g  = fmaf(fr, ab.y, ab.x);
                k = fmaf(g, q, kk);
                zt[c] = k;                          // raw k; drain applies 2.1x
            }
        } else {
            // ---- I/O warp ----
            if (t + 2 < NTILES) {
                prefetch_tile(u, b0, t + 2, u_s[t & 1], lane);
                asm volatile("cp.async.commit_group;" ::: "memory");
                asm volatile("cp.async.wait_group 1;" ::: "memory");
            } else {
                asm volatile("cp.async.wait_group 0;" ::: "memory");
            }
            if (t + 1 < NTILES) {
                // Build pairs for tile t+1 from u_s[(t+1)&1]: lane = row
                const float* us = u_s[(t + 1) & 1];
                float2* pp = &pair_s[(t + 1) & 1][lane * 33];
                #pragma unroll
                for (int c = 0; c < 32; ++c) {
                    float uin = us[lane * 33 + c];
                    W = fmaf(0.8f, W, uin);
                    pp[c] = make_float2(fmaf(uin, uin, EPS_S), 0.104f * W);
                }
            }
            if (t > 0) {
                // Drain z tile t-1: r = row, lane = time
                const float* zs = z_s[(t - 1) & 1];
                float* dst = out + (size_t)b0 * (T_LEN + 1) + 1
                           + (size_t)(t - 1) * 32 + lane;
                #pragma unroll
                for (int r = 0; r < 32; ++r)
                    dst[(size_t)r * (T_LEN + 1)] = 2.1f * zs[r * 33 + lane];
            }
        }
        __syncthreads();
    }

    if (wid == 1) {
        const float* zs = z_s[(NTILES - 1) & 1];
        float* dst = out + (size_t)b0 * (T_LEN + 1) + 1
                   + (size_t)(NTILES - 1) * 32 + lane;
        #pragma unroll
        for (int r = 0; r < 32; ++r)
            dst[(size_t)r * (T_LEN + 1)] = 2.1f * zs[r * 33 + lane];
    }
}

// ---------------------------------------------------------------------------
extern "C" void kernel_launch(void* const* d_in, const int* in_sizes, int n_in,
                              void* d_out, int out_size) {
    const float* u = (const float*)d_in[0];
    float* out = (float*)d_out;
    (void)in_sizes; (void)n_in; (void)out_size;

    build_bounds_kernel<<<NB, 32>>>();
    build_lut_kernel<<<(NLUT + 255) / 256, 256>>>();
    scan_kernel<<<B_LEN / 32, 64>>>(u, out);
}

// round 9
// speedup vs baseline: 1.9609x; 1.3586x over previous
#include <cuda_runtime.h>
#include <cstdint>

// Problem constants (fixed shapes for this problem)
#define T_LEN 4096
#define B_LEN 4096
#define NTILES (T_LEN / 32)

// LUT: log2-spaced piecewise-linear table of
//   g(s) = (1/sqrt(2pi)) * int_{-5}^{5} (1 - tanh(sqrt(s)*z)^2) exp(-z^2/2) dz
// indexed directly by float bits of s. 64 bins/octave, s in [2^-14, 2^8).
#define OCTAVES 22
#define NLUT (OCTAVES * 64)       // 1408
#define BASE_BITS 0x38800000u     // float bits of 2^-14
#define BASE_OFF  57856u          // BASE_BITS >> 14
#define EPS_S 6.103515625e-05f    // 2^-14, added to u^2 so s >= 2^-14 always

__device__ float2 g_lut[NLUT];

// ---------------------------------------------------------------------------
// Single build kernel: block j computes g at bin endpoints j and j+1
// (half-warp each) via composite Simpson on [0,5] (even integrand -> x2),
// n=1024 intervals, f32 evals, double accumulation; writes (value, slope).
// ---------------------------------------------------------------------------
__global__ void build_lut_combined() {
    int j = blockIdx.x;            // 0 .. NLUT-1
    int lane = threadIdx.x;        // 32
    int half = lane >> 4;          // 0 -> endpoint j, 1 -> endpoint j+1
    int hl = lane & 15;
    unsigned bits = BASE_BITS + ((unsigned)(j + half) << 17);
    float delta = sqrtf(__uint_as_float(bits));

    const int   n = 1024;
    const float h = 5.0f / (float)n;
    double acc = 0.0;
    for (int i = hl; i <= n; i += 16) {
        float z = h * (float)i;
        float t = tanhf(delta * z);
        float f = (1.0f - t * t) * expf(-0.5f * z * z);
        float coef = (i == 0 || i == n) ? 1.0f : ((i & 1) ? 4.0f : 2.0f);
        acc += (double)(f * coef);
    }
    // reduce within each 16-lane half (xor keeps lanes inside their half)
    #pragma unroll
    for (int o = 8; o; o >>= 1)
        acc += __shfl_xor_sync(0xffffffffu, acc, o);
    double g = acc * ((double)h / 3.0) * 2.0 * 0.3989422804014327;
    float g0 = (float)__shfl_sync(0xffffffffu, g, 0);
    float g1 = (float)__shfl_sync(0xffffffffu, g, 16);
    if (lane == 0)
        g_lut[j] = make_float2(g0, (g1 - g0) * (1.0f / 131072.0f));
}

// ---------------------------------------------------------------------------
// Warp-specialized scan. Block = 64 threads.
// u_s layout (written by prefetch_tile): [row*33 + time].
//   warp 0: k-chain only, pairs burst-loaded to registers at tile start,
//           z accumulated in registers, burst STS at tile end. Step chain:
//       s=FFMA(k,k,uu) -> SHF -> LOP3 -> LDS.64(lut) -> FFMA(g) -> FFMA(k)
//   warp 1: cp.async u prefetch; v/W recurrence ONE TILE AHEAD writing
//           (uu, r)=(u^2+eps, 0.104*W) pairs; z drain (applies 2.1x).
// One __syncthreads() per 32-step tile.
// ---------------------------------------------------------------------------
__device__ __forceinline__ void prefetch_tile(const float* __restrict__ u,
                                              int b0, int tile,
                                              float* ubuf, int lane) {
    const float* src = u + (size_t)b0 * T_LEN + (size_t)tile * 32 + lane;
    unsigned sbase = (unsigned)__cvta_generic_to_shared(ubuf);
    #pragma unroll
    for (int r = 0; r < 32; ++r) {
        // row r, time lane -> ubuf[r*33 + lane]
        unsigned d = sbase + (unsigned)((r * 33 + lane) * 4);
        const float* s = src + (size_t)r * T_LEN;
        asm volatile("cp.async.ca.shared.global [%0], [%1], 4;" :: "r"(d), "l"(s));
    }
}

__global__ __launch_bounds__(64, 1)
void scan_kernel(const float* __restrict__ u, float* __restrict__ out) {
    __shared__ float2 lut_s[NLUT];         // 11264 B
    __shared__ float  u_s[2][32 * 33];     // 8448 B  [row*33 + time]
    __shared__ float2 pair_s[2][32 * 33];  // 16896 B [row*33 + time] = (uu, r)
    __shared__ float  z_s[2][32 * 33];     // 8448 B  [row*33 + time], raw k

    int tid  = threadIdx.x;
    int lane = tid & 31;
    int wid  = tid >> 5;
    int b0 = blockIdx.x * 32;

    // Cooperative LUT stage (both warps, float4 copies)
    {
        const float4* src = (const float4*)g_lut;     // NLUT*8/16 = 704
        float4* dst = (float4*)lut_s;
        for (int i = tid; i < NLUT / 2; i += 64) dst[i] = src[i];
    }

    float W = 0.0f;  // I/O warp's v-state: v = 0.2*W, W <- 0.8*W + u

    if (wid == 1) {
        prefetch_tile(u, b0, 0, u_s[0], lane);
        asm volatile("cp.async.commit_group;" ::: "memory");
        prefetch_tile(u, b0, 1, u_s[1], lane);
        asm volatile("cp.async.commit_group;" ::: "memory");
        asm volatile("cp.async.wait_group 1;" ::: "memory");
        // Build pairs for tile 0: lane = row, c = time
        float2* pp = &pair_s[0][lane * 33];
        #pragma unroll
        for (int c = 0; c < 32; ++c) {
            float uin = u_s[0][lane * 33 + c];
            W = fmaf(0.8f, W, uin);
            pp[c] = make_float2(fmaf(uin, uin, EPS_S), 0.104f * W);
        }
    } else {
        out[(size_t)(b0 + lane) * (T_LEN + 1)] = 0.0f;  // z_hist[:,0] = 0
    }
    __syncthreads();

    float k = 0.0f;

    #pragma unroll 1
    for (int t = 0; t < NTILES; ++t) {
        if (wid == 0) {
            // ---- compute warp: burst-load pairs, 32 register-only chain
            //      steps, burst-store z ----
            const float2* __restrict__ pp = &pair_s[t & 1][lane * 33];
            float2 prbuf[32];
            #pragma unroll
            for (int c = 0; c < 32; ++c) prbuf[c] = pp[c];

            float zbuf[32];
            #pragma unroll
            for (int c = 0; c < 32; ++c) {
                float2 pr = prbuf[c];
                float q  = fmaf(0.28f, k, pr.y);
                float kk = 0.8f * k;
                float s  = fmaf(k, k, pr.x);
                unsigned bits = __float_as_uint(s);
                unsigned off  = (bits >> 14) & 0x1FFF8u;
                float2 ab = *(const float2*)((const char*)lut_s + (off - BASE_OFF));
                float fr = __uint2float_rn(bits & 0x1FFFFu);
                float g  = fmaf(fr, ab.y, ab.x);
                k = fmaf(g, q, kk);
                zbuf[c] = k;
            }

            float* __restrict__ zt = &z_s[t & 1][lane * 33];
            #pragma unroll
            for (int c = 0; c < 32; ++c) zt[c] = zbuf[c];
        } else {
            // ---- I/O warp ----
            if (t + 2 < NTILES) {
                prefetch_tile(u, b0, t + 2, u_s[t & 1], lane);
                asm volatile("cp.async.commit_group;" ::: "memory");
                asm volatile("cp.async.wait_group 1;" ::: "memory");
            } else {
                asm volatile("cp.async.wait_group 0;" ::: "memory");
            }
            if (t + 1 < NTILES) {
                // Build pairs for tile t+1 from u_s[(t+1)&1]: lane = row
                const float* us = u_s[(t + 1) & 1];
                float2* pp = &pair_s[(t + 1) & 1][lane * 33];
                #pragma unroll
                for (int c = 0; c < 32; ++c) {
                    float uin = us[lane * 33 + c];
                    W = fmaf(0.8f, W, uin);
                    pp[c] = make_float2(fmaf(uin, uin, EPS_S), 0.104f * W);
                }
            }
            if (t > 0) {
                // Drain z tile t-1: r = row, lane = time
                const float* zs = z_s[(t - 1) & 1];
                float* dst = out + (size_t)b0 * (T_LEN + 1) + 1
                           + (size_t)(t - 1) * 32 + lane;
                #pragma unroll
                for (int r = 0; r < 32; ++r)
                    dst[(size_t)r * (T_LEN + 1)] = 2.1f * zs[r * 33 + lane];
            }
        }
        __syncthreads();
    }

    if (wid == 1) {
        const float* zs = z_s[(NTILES - 1) & 1];
        float* dst = out + (size_t)b0 * (T_LEN + 1) + 1
                   + (size_t)(NTILES - 1) * 32 + lane;
        #pragma unroll
        for (int r = 0; r < 32; ++r)
            dst[(size_t)r * (T_LEN + 1)] = 2.1f * zs[r * 33 + lane];
    }
}

// ---------------------------------------------------------------------------
extern "C" void kernel_launch(void* const* d_in, const int* in_sizes, int n_in,
                              void* d_out, int out_size) {
    const float* u = (const float*)d_in[0];
    float* out = (float*)d_out;
    (void)in_sizes; (void)n_in; (void)out_size;

    build_lut_combined<<<NLUT, 32>>>();
    scan_kernel<<<B_LEN / 32, 64>>>(u, out);
}

// round 10
// speedup vs baseline: 2.0694x; 1.0553x over previous
#include <cuda_runtime.h>
#include <cstdint>

// Problem constants (fixed shapes for this problem)
#define T_LEN 4096
#define B_LEN 4096
#define NTILES (T_LEN / 32)

// LUT: log2-spaced midpoint-value table of
//   g(s) = (1/sqrt(2pi)) * int_{-5}^{5} (1 - tanh(sqrt(s)*z)^2) exp(-z^2/2) dz
// indexed directly by float bits of s. 256 bins/octave, s in [2^-14, 2^8).
#define OCTAVES 22
#define NLUT (OCTAVES * 256)      // 5632 entries, f32
#define BASE_BITS 0x38800000u     // float bits of 2^-14
#define BASE_OFF  115712u         // BASE_BITS >> 13
#define EPS_S 6.103515625e-05f    // 2^-14, added to u^2 so s >= 2^-14 always

__device__ float g_lut[NLUT];

// ---------------------------------------------------------------------------
// Build kernel: block j computes g at the BIT-midpoint of bin j via composite
// Simpson on [0,5] (even integrand -> x2), f32 evals, double accumulation.
// Adaptive n: integrand width ~1/delta, so only large-delta bins need n=1024.
// ---------------------------------------------------------------------------
__global__ void build_lut_kernel() {
    int j = blockIdx.x;            // 0 .. NLUT-1
    int lane = threadIdx.x;        // 32
    unsigned bits = BASE_BITS + ((unsigned)j << 15) + (1u << 14);  // bin midpoint
    float delta = sqrtf(__uint_as_float(bits));

    int n = (delta > 4.0f) ? 1024 : 256;
    float h = 5.0f / (float)n;
    double acc = 0.0;
    for (int i = lane; i <= n; i += 32) {
        float z = h * (float)i;
        float t = tanhf(delta * z);
        float f = (1.0f - t * t) * expf(-0.5f * z * z);
        float coef = (i == 0 || i == n) ? 1.0f : ((i & 1) ? 4.0f : 2.0f);
        acc += (double)(f * coef);
    }
    #pragma unroll
    for (int o = 16; o; o >>= 1)
        acc += __shfl_down_sync(0xffffffffu, acc, o);
    if (lane == 0)
        g_lut[j] = (float)(acc * ((double)h / 3.0) * 2.0 * 0.3989422804014327);
}

// ---------------------------------------------------------------------------
// Warp-specialized scan. Block = 64 threads.
//   warp 0: k-chain only; pairs burst-loaded to registers at tile start,
//           z accumulated in registers, burst STS at tile end. Step chain:
//       s=FFMA(k,k,uu) -> SHF -> LOP3 -> LDS.32(lut) -> FFMA(k)
//   warp 1: direct __ldg of u (one 128B line per lane per tile, register
//           double-buffered one tile ahead); v/W recurrence ONE TILE AHEAD
//           writing (uu, r)=(u^2+eps, 0.104*W) pairs; z drain (applies 2.1x).
// One __syncthreads() per 32-step tile.
// ---------------------------------------------------------------------------
__global__ __launch_bounds__(64, 1)
void scan_kernel(const float* __restrict__ u, float* __restrict__ out) {
    __shared__ float  lut_s[NLUT];         // 22528 B
    __shared__ float2 pair_s[2][32 * 33];  // 16896 B [row*33 + time] = (uu, r)
    __shared__ float  z_s[2][32 * 33];     // 8448 B  [row*33 + time], raw k

    int tid  = threadIdx.x;
    int lane = tid & 31;
    int wid  = tid >> 5;
    int b0 = blockIdx.x * 32;

    // Cooperative LUT stage (both warps, float4 copies)
    {
        const float4* src = (const float4*)g_lut;     // NLUT/4 = 1408
        float4* dst = (float4*)lut_s;
        for (int i = tid; i < NLUT / 4; i += 64) dst[i] = src[i];
    }

    float W = 0.0f;  // I/O warp's v-state: v = 0.2*W, W <- 0.8*W + u
    const float4* __restrict__ urow =
        (const float4*)(u + (size_t)(b0 + lane) * T_LEN);
    float4 ubuf[8];

    if (wid == 1) {
        // Load u tile 0, build pairs for tile 0, then preload u tile 1.
        #pragma unroll
        for (int j = 0; j < 8; ++j) ubuf[j] = __ldg(urow + j);
        float2* pp = &pair_s[0][lane * 33];
        #pragma unroll
        for (int j = 0; j < 8; ++j) {
            float uv[4] = {ubuf[j].x, ubuf[j].y, ubuf[j].z, ubuf[j].w};
            #pragma unroll
            for (int q4 = 0; q4 < 4; ++q4) {
                float uin = uv[q4];
                W = fmaf(0.8f, W, uin);
                pp[j * 4 + q4] = make_float2(fmaf(uin, uin, EPS_S), 0.104f * W);
            }
        }
        #pragma unroll
        for (int j = 0; j < 8; ++j) ubuf[j] = __ldg(urow + 8 + j);
    } else {
        out[(size_t)(b0 + lane) * (T_LEN + 1)] = 0.0f;  // z_hist[:,0] = 0
    }
    __syncthreads();

    float k = 0.0f;

    #pragma unroll 1
    for (int t = 0; t < NTILES; ++t) {
        if (wid == 0) {
            // ---- compute warp: burst-load pairs, 32 register-only chain
            //      steps, burst-store z ----
            const float2* __restrict__ pp = &pair_s[t & 1][lane * 33];
            float2 prbuf[32];
            #pragma unroll
            for (int c = 0; c < 32; ++c) prbuf[c] = pp[c];

            float zbuf[32];
            #pragma unroll
            for (int c = 0; c < 32; ++c) {
                float2 pr = prbuf[c];
                float q  = fmaf(0.28f, k, pr.y);
                float kk = 0.8f * k;
                float s  = fmaf(k, k, pr.x);
                unsigned bits = __float_as_uint(s);
                unsigned off  = (bits >> 13) & 0x7FFFCu;
                float g = *(const float*)((const char*)lut_s + (off - BASE_OFF));
                k = fmaf(g, q, kk);
                zbuf[c] = k;
            }

            float* __restrict__ zt = &z_s[t & 1][lane * 33];
            #pragma unroll
            for (int c = 0; c < 32; ++c) zt[c] = zbuf[c];
        } else {
            // ---- I/O warp ----
            if (t + 1 < NTILES) {
                // Build pairs for tile t+1 from register-buffered u
                float2* pp = &pair_s[(t + 1) & 1][lane * 33];
                #pragma unroll
                for (int j = 0; j < 8; ++j) {
                    float uv[4] = {ubuf[j].x, ubuf[j].y, ubuf[j].z, ubuf[j].w};
                    #pragma unroll
                    for (int q4 = 0; q4 < 4; ++q4) {
                        float uin = uv[q4];
                        W = fmaf(0.8f, W, uin);
                        pp[j * 4 + q4] =
                            make_float2(fmaf(uin, uin, EPS_S), 0.104f * W);
                    }
                }
                // Prefetch u for tile t+2 (plenty of latency slack)
                if (t + 2 < NTILES) {
                    #pragma unroll
                    for (int j = 0; j < 8; ++j)
                        ubuf[j] = __ldg(urow + (size_t)(t + 2) * 8 + j);
                }
            }
            if (t > 0) {
                // Drain z tile t-1: r = row, lane = time (coalesced per r)
                const float* zs = z_s[(t - 1) & 1];
                float* dst = out + (size_t)b0 * (T_LEN + 1) + 1
                           + (size_t)(t - 1) * 32 + lane;
                #pragma unroll
                for (int r = 0; r < 32; ++r)
                    dst[(size_t)r * (T_LEN + 1)] = 2.1f * zs[r * 33 + lane];
            }
        }
        __syncthreads();
    }

    if (wid == 1) {
        const float* zs = z_s[(NTILES - 1) & 1];
        float* dst = out + (size_t)b0 * (T_LEN + 1) + 1
                   + (size_t)(NTILES - 1) * 32 + lane;
        #pragma unroll
        for (int r = 0; r < 32; ++r)
            dst[(size_t)r * (T_LEN + 1)] = 2.1f * zs[r * 33 + lane];
    }
}

// ---------------------------------------------------------------------------
extern "C" void kernel_launch(void* const* d_in, const int* in_sizes, int n_in,
                              void* d_out, int out_size) {
    const float* u = (const float*)d_in[0];
    float* out = (float*)d_out;
    (void)in_sizes; (void)n_in; (void)out_size;

    build_lut_kernel<<<NLUT, 32>>>();
    scan_kernel<<<B_LEN / 32, 64>>>(u, out);
}